// round 1
// baseline (speedup 1.0000x reference)
#include <cuda_runtime.h>

// ComposeTransform: out = compose(compose(w1, w2), w3) of dense displacement
// fields [B=2, D=128, H=128, W=128, C=3], trilinear sampling with clamp.
//
// u_ab(x)  = w1(x) + trilerp(w2, x + w1(x))
// out(x)   = u_ab(x) + trilerp(w3, x + u_ab(x))

#define DIMX 128
#define NC 3
#define SX (DIMX*DIMX*NC)   // stride for dim0 (D)
#define SY (DIMX*NC)        // stride for dim1 (H)
#define VOX (DIMX*DIMX*DIMX)

__device__ __forceinline__ void trilerp(const float* __restrict__ vol,
                                        float lx, float ly, float lz,
                                        float& ox, float& oy, float& oz) {
    const float M = (float)(DIMX - 1);
    lx = fminf(fmaxf(lx, 0.0f), M);
    ly = fminf(fmaxf(ly, 0.0f), M);
    lz = fminf(fmaxf(lz, 0.0f), M);
    float fx0 = floorf(lx), fy0 = floorf(ly), fz0 = floorf(lz);
    int ix0 = (int)fx0, iy0 = (int)fy0, iz0 = (int)fz0;
    int ix1 = min(ix0 + 1, DIMX - 1);
    int iy1 = min(iy0 + 1, DIMX - 1);
    int iz1 = min(iz0 + 1, DIMX - 1);
    float fx = lx - fx0, fy = ly - fy0, fz = lz - fz0;
    float gx = 1.0f - fx, gy = 1.0f - fy, gz = 1.0f - fz;

    const float* px0 = vol + ix0 * SX;
    const float* px1 = vol + ix1 * SX;
    const float* p00 = px0 + iy0 * SY;
    const float* p01 = px0 + iy1 * SY;
    const float* p10 = px1 + iy0 * SY;
    const float* p11 = px1 + iy1 * SY;
    int z0 = iz0 * NC, z1 = iz1 * NC;

    float w00 = gx * gy, w01 = gx * fy, w10 = fx * gy, w11 = fx * fy;

    float acx = 0.0f, acy = 0.0f, acz = 0.0f;
#define CORNER(P, WXY, ZOFF, WZ) { \
        float w = (WXY) * (WZ); \
        const float* q = (P) + (ZOFF); \
        acx = fmaf(w, __ldg(q + 0), acx); \
        acy = fmaf(w, __ldg(q + 1), acy); \
        acz = fmaf(w, __ldg(q + 2), acz); }
    CORNER(p00, w00, z0, gz)
    CORNER(p00, w00, z1, fz)
    CORNER(p01, w01, z0, gz)
    CORNER(p01, w01, z1, fz)
    CORNER(p10, w10, z0, gz)
    CORNER(p10, w10, z1, fz)
    CORNER(p11, w11, z0, gz)
    CORNER(p11, w11, z1, fz)
#undef CORNER
    ox = acx; oy = acy; oz = acz;
}

extern "C" __global__ void __launch_bounds__(256)
compose_transform_kernel(const float* __restrict__ w1,
                         const float* __restrict__ w2,
                         const float* __restrict__ w3,
                         float* __restrict__ out,
                         int total) {
    int gid = blockIdx.x * blockDim.x + threadIdx.x;
    if (gid >= total) return;

    int b = gid >> 21;                 // VOX = 2^21
    int v = gid & (VOX - 1);
    int z = v & (DIMX - 1);            // W index (fastest)
    int y = (v >> 7) & (DIMX - 1);     // H index
    int x = v >> 14;                   // D index

    int base = b * (VOX * NC);
    const float* W1 = w1 + base;
    const float* W2 = w2 + base;
    const float* W3 = w3 + base;
    float* O = out + base;

    int off = v * NC;
    float d0 = W1[off + 0];
    float d1 = W1[off + 1];
    float d2 = W1[off + 2];

    float sx, sy, sz;
    trilerp(W2, (float)x + d0, (float)y + d1, (float)z + d2, sx, sy, sz);
    float u0 = d0 + sx, u1 = d1 + sy, u2 = d2 + sz;

    trilerp(W3, (float)x + u0, (float)y + u1, (float)z + u2, sx, sy, sz);

    O[off + 0] = u0 + sx;
    O[off + 1] = u1 + sy;
    O[off + 2] = u2 + sz;
}

extern "C" void kernel_launch(void* const* d_in, const int* in_sizes, int n_in,
                              void* d_out, int out_size) {
    const float* w1 = (const float*)d_in[0];
    const float* w2 = (const float*)d_in[1];
    const float* w3 = (const float*)d_in[2];
    float* out = (float*)d_out;

    int total = in_sizes[0] / NC;      // B * 128^3 voxels
    int threads = 256;
    int blocks = (total + threads - 1) / threads;
    compose_transform_kernel<<<blocks, threads>>>(w1, w2, w3, out, total);
}

// round 3
// speedup vs baseline: 1.1174x; 1.1174x over previous
#include <cuda_runtime.h>

// ComposeTransform: out = compose(compose(w1, w2), w3) of dense displacement
// fields [B=2, D=128, H=128, W=128, C=3], trilinear sampling with clamp.
//
// Strategy: the compose kernel is L1tex-wavefront bound (round-1 ncu:
// L1=89.8%, DRAM=10.3%). Repack the two gather sources (w2, w3) into
// channel-padded float4 volumes so every trilerp corner is a single LDG.128
// instead of 3x LDG.32.

#define DIMX 128
#define NC 3
#define VOX (DIMX*DIMX*DIMX)     // 2^21
#define NBATCH 2

// Scratch: padded copies of w2 and w3 (both batches), one symbol.
// layout: [vol(0=w2,1=w3)][batch][voxel] -> float4.   2*2*VOX*16B = 128 MB.
__device__ float4 g_pad[2 * NBATCH * VOX];

// ---------------------------------------------------------------------------
// Repack: [.., 3] float -> [.., 4] float4 (w unused). Fully vectorized:
// each thread reads 3 float4 (= 4 voxels) and writes 4 float4.
// Grid covers both volumes: volume id = t / n4.
// ---------------------------------------------------------------------------
extern "C" __global__ void __launch_bounds__(256)
repack_kernel(const float4* __restrict__ w2, const float4* __restrict__ w3,
              int n4 /* = NBATCH*VOX/4 */) {
    int t = blockIdx.x * blockDim.x + threadIdx.x;
    int volid = (t >= n4) ? 1 : 0;
    int tt = t - volid * n4;
    if (tt >= n4) return;
    const float4* src = volid ? w3 : w2;
    float4* dst = g_pad + volid * (NBATCH * VOX);

    float4 a = __ldg(src + 3 * tt + 0);
    float4 b = __ldg(src + 3 * tt + 1);
    float4 c = __ldg(src + 3 * tt + 2);
    dst[4 * tt + 0] = make_float4(a.x, a.y, a.z, 0.0f);
    dst[4 * tt + 1] = make_float4(a.w, b.x, b.y, 0.0f);
    dst[4 * tt + 2] = make_float4(b.z, b.w, c.x, 0.0f);
    dst[4 * tt + 3] = make_float4(c.y, c.z, c.w, 0.0f);
}

// ---------------------------------------------------------------------------
// Trilinear sample from a padded float4 volume. One LDG.128 per corner.
// ---------------------------------------------------------------------------
__device__ __forceinline__ void trilerp4(const float4* __restrict__ vol,
                                         float lx, float ly, float lz,
                                         float& ox, float& oy, float& oz) {
    const float M = (float)(DIMX - 1);
    lx = fminf(fmaxf(lx, 0.0f), M);
    ly = fminf(fmaxf(ly, 0.0f), M);
    lz = fminf(fmaxf(lz, 0.0f), M);
    int ix0 = __float2int_rd(lx);
    int iy0 = __float2int_rd(ly);
    int iz0 = __float2int_rd(lz);
    float fx = lx - (float)ix0, fy = ly - (float)iy0, fz = lz - (float)iz0;
    int ix1 = min(ix0 + 1, DIMX - 1);
    int iy1 = min(iy0 + 1, DIMX - 1);
    int iz1 = min(iz0 + 1, DIMX - 1);
    float gx = 1.0f - fx, gy = 1.0f - fy, gz = 1.0f - fz;

    int b00 = (ix0 << 14) + (iy0 << 7);
    int b01 = (ix0 << 14) + (iy1 << 7);
    int b10 = (ix1 << 14) + (iy0 << 7);
    int b11 = (ix1 << 14) + (iy1 << 7);

    float w00 = gx * gy, w01 = gx * fy, w10 = fx * gy, w11 = fx * fy;

    float acx = 0.0f, acy = 0.0f, acz = 0.0f;
#define CORNER(BASE, WXY, IZ, WZ) { \
        float w = (WXY) * (WZ); \
        float4 v = __ldg(vol + (BASE) + (IZ)); \
        acx = fmaf(w, v.x, acx); \
        acy = fmaf(w, v.y, acy); \
        acz = fmaf(w, v.z, acz); }
    CORNER(b00, w00, iz0, gz)
    CORNER(b00, w00, iz1, fz)
    CORNER(b01, w01, iz0, gz)
    CORNER(b01, w01, iz1, fz)
    CORNER(b10, w10, iz0, gz)
    CORNER(b10, w10, iz1, fz)
    CORNER(b11, w11, iz0, gz)
    CORNER(b11, w11, iz1, fz)
#undef CORNER
    ox = acx; oy = acy; oz = acz;
}

// ---------------------------------------------------------------------------
// Main compose kernel: one thread per voxel.
// ---------------------------------------------------------------------------
extern "C" __global__ void __launch_bounds__(256)
compose_transform_kernel(const float* __restrict__ w1,
                         float* __restrict__ out) {
    int gid = blockIdx.x * blockDim.x + threadIdx.x;

    int b = gid >> 21;                 // VOX = 2^21
    int v = gid & (VOX - 1);
    int z = v & (DIMX - 1);
    int y = (v >> 7) & (DIMX - 1);
    int x = v >> 14;

    const float4* W2 = g_pad + b * VOX;
    const float4* W3 = g_pad + (NBATCH + b) * VOX;

    int off = gid * NC;
    float d0 = w1[off + 0];
    float d1 = w1[off + 1];
    float d2 = w1[off + 2];

    float sx, sy, sz;
    trilerp4(W2, (float)x + d0, (float)y + d1, (float)z + d2, sx, sy, sz);
    float u0 = d0 + sx, u1 = d1 + sy, u2 = d2 + sz;

    trilerp4(W3, (float)x + u0, (float)y + u1, (float)z + u2, sx, sy, sz);

    out[off + 0] = u0 + sx;
    out[off + 1] = u1 + sy;
    out[off + 2] = u2 + sz;
}

extern "C" void kernel_launch(void* const* d_in, const int* in_sizes, int n_in,
                              void* d_out, int out_size) {
    const float* w1 = (const float*)d_in[0];
    const float4* w2 = (const float4*)d_in[1];
    const float4* w3 = (const float4*)d_in[2];
    float* out = (float*)d_out;

    int n4 = (NBATCH * VOX) / 4;          // float4-group count per volume
    int rep_threads = 2 * n4;             // both volumes
    repack_kernel<<<(rep_threads + 255) / 256, 256>>>(w2, w3, n4);

    int total = NBATCH * VOX;
    compose_transform_kernel<<<(total + 255) / 256, 256>>>(w1, out);
}